// round 5
// baseline (speedup 1.0000x reference)
#include <cuda_runtime.h>

#define BB 4
#define CC 64
#define TNT 128          // n-tiles per batch (TN=32)
#define TN 32
#define NN 4096
#define GRID 512

typedef unsigned long long ull;

// scratch (allocation-free rule: __device__ globals, zero-initialized)
__device__ float g_a[BB * NN];
__device__ float g_d[BB * NN];
__device__ float g_upart[2 * BB * CC];
__device__ float g_vpart[2 * BB * CC];
__device__ float g_W0t[CC * CC];     // [c][o]
__device__ float g_W1t[CC * CC];     // [c][o]
__device__ float g_scale[CC];
__device__ float g_shift[CC];
__device__ unsigned g_bar;           // monotonic barrier counter

// ---- f32x2 packed helpers ---------------------------------------------------
__device__ __forceinline__ ull pack2(float lo, float hi) {
    ull r; asm("mov.b64 %0, {%1, %2};" : "=l"(r) : "f"(lo), "f"(hi)); return r;
}
__device__ __forceinline__ void unpack2(ull v, float& lo, float& hi) {
    asm("mov.b64 {%0, %1}, %2;" : "=f"(lo), "=f"(hi) : "l"(v));
}
__device__ __forceinline__ ull fma2(ull a, ull b, ull c) {
    ull d; asm("fma.rn.f32x2 %0, %1, %2, %3;" : "=l"(d) : "l"(a), "l"(b), "l"(c)); return d;
}

__device__ __forceinline__ float relutanh(float x) {
    if (x <= 0.f) return 0.f;
    float e = __expf(-2.f * x);
    return (1.f - e) * __frcp_rn(1.f + e);
}

// -----------------------------------------------------------------------------
// Single fused kernel, grid=512, 256 threads, 48KB dynamic smem, <=64 regs.
// Phase 1: blk -> (b = blk>>7, c = (blk&127)>>1, h = blk&1).
//   Computes a (full N, regs) + S + d; reduces u,v over half h of N -> g_*part.
//   blk==b<<7 writes g_a/g_d; b==0,h==0 blocks transpose conv_w row c;
//   blk==0 folds BN.
// Barrier: device-wide monotonic counter.
// Phase 2: blk -> (b = blk>>7, tile = blk&127), n0 = tile*32.
//   warp = 8 o, lane = 1 n. o-pair packed f32x2 GEMM + rank-1 + BN + ReLU.
// -----------------------------------------------------------------------------
__global__ void __launch_bounds__(256, 4) k_fused(
        const float* __restrict__ x,
        const float* __restrict__ w,
        const float* __restrict__ conv_w,
        const float* __restrict__ conv_b,
        const float* __restrict__ gamma,
        const float* __restrict__ beta,
        const float* __restrict__ mean,
        const float* __restrict__ var,
        float* __restrict__ out) {
    extern __shared__ float sm[];
    float* xs  = sm;                  // [64][64] dup {x,x}   16KB
    float* w0s = sm + CC * 2 * TN;    // [64][64]             16KB
    float* w1s = w0s + CC * CC;       //                      16KB
    __shared__ float p_s[CC], q_s[CC], u_s[CC], v_s[CC];
    __shared__ float red[8], red2[8];
    __shared__ float S_sh;

    const int tid = threadIdx.x;
    const int blk = blockIdx.x;
    const int b = blk >> 7;

    // ================= Phase 1 =================
    {
        const int idx = blk & 127;
        const int c = idx >> 1;
        const int h = idx & 1;

        const float4* w4 = (const float4*)(w + b * NN);
        float avr[16], dvr[16];
        float s = 0.f;
        #pragma unroll
        for (int k = 0; k < 4; k++) {
            float4 wv = w4[tid + k * 256];
            avr[k*4+0] = relutanh(wv.x);
            avr[k*4+1] = relutanh(wv.y);
            avr[k*4+2] = relutanh(wv.z);
            avr[k*4+3] = relutanh(wv.w);
            s += avr[k*4+0] + avr[k*4+1] + avr[k*4+2] + avr[k*4+3];
        }
        #pragma unroll
        for (int off = 16; off; off >>= 1) s += __shfl_down_sync(0xffffffffu, s, off);
        if ((tid & 31) == 0) red[tid >> 5] = s;
        __syncthreads();
        if (tid == 0) {
            float t = 0.f;
            #pragma unroll
            for (int i = 0; i < 8; i++) t += red[i];
            S_sh = t;
        }
        __syncthreads();
        const float S = S_sh;
        #pragma unroll
        for (int i = 0; i < 16; i++) dvr[i] = rsqrtf(fmaf(avr[i], S, 1.f));

        if (idx == 0) {
            #pragma unroll
            for (int k = 0; k < 4; k++) {
                ((float4*)(g_a + b * NN))[tid + k * 256] =
                    make_float4(avr[k*4+0], avr[k*4+1], avr[k*4+2], avr[k*4+3]);
                ((float4*)(g_d + b * NN))[tid + k * 256] =
                    make_float4(dvr[k*4+0], dvr[k*4+1], dvr[k*4+2], dvr[k*4+3]);
            }
        }
        if (b == 0 && h == 0) {
            if (tid < CC) {
                g_W0t[c * CC + tid] = conv_w[tid * 128 + c];
                g_W1t[c * CC + tid] = conv_w[tid * 128 + CC + c];
            }
            if (c == 0 && tid >= 64 && tid < 128) {
                int o = tid - 64;
                float sc = gamma[o] * rsqrtf(var[o] + 1e-5f);
                g_scale[o] = sc;
                g_shift[o] = fmaf(conv_b[o] - mean[o], sc, beta[o]);
            }
        }

        // partial u,v over half h
        const float4* x4 = (const float4*)(x + (size_t)(b * CC + c) * NN);
        float su = 0.f, sv = 0.f;
        #pragma unroll
        for (int kk = 0; kk < 2; kk++) {
            int k = 2 * h + kk;
            float4 xv = x4[tid + k * 256];
            float t0 = xv.x * avr[k*4+0], t1 = xv.y * avr[k*4+1];
            float t2 = xv.z * avr[k*4+2], t3 = xv.w * avr[k*4+3];
            su += t0 + t1 + t2 + t3;
            sv += t0 * dvr[k*4+0] + t1 * dvr[k*4+1] + t2 * dvr[k*4+2] + t3 * dvr[k*4+3];
        }
        #pragma unroll
        for (int off = 16; off; off >>= 1) {
            su += __shfl_down_sync(0xffffffffu, su, off);
            sv += __shfl_down_sync(0xffffffffu, sv, off);
        }
        if ((tid & 31) == 0) { red[tid >> 5] = su; red2[tid >> 5] = sv; }
        __syncthreads();
        if (tid == 0) {
            float tu = 0.f, tv = 0.f;
            #pragma unroll
            for (int i = 0; i < 8; i++) { tu += red[i]; tv += red2[i]; }
            g_upart[h * BB * CC + b * CC + c] = tu;
            g_vpart[h * BB * CC + b * CC + c] = tv;
        }
    }

    // ================= device-wide barrier =================
    __threadfence();
    __syncthreads();
    if (tid == 0) {
        unsigned old = atomicAdd(&g_bar, 1u);
        unsigned target = (old & ~(unsigned)(GRID - 1)) + GRID;
        unsigned vcur;
        do { vcur = *(volatile unsigned*)&g_bar; } while ((int)(vcur - target) < 0);
    }
    __syncthreads();

    // ================= Phase 2 =================
    const int tile = blk & 127;
    const int n0 = tile * TN;

    // stage: x duplicated [c][2n], weights, u/v
    {
        const float* xb = x + (size_t)(b * CC) * NN + n0;
        #pragma unroll
        for (int k = 0; k < 8; k++) {
            int i = tid + k * 256;          // 0..2047
            int c = i >> 5, l = i & 31;
            float val = xb[c * NN + l];
            *(float2*)(xs + c * 2 * TN + 2 * l) = make_float2(val, val);
        }
        float4* w0s4 = (float4*)w0s;
        float4* w1s4 = (float4*)w1s;
        const float4* gw0 = (const float4*)g_W0t;
        const float4* gw1 = (const float4*)g_W1t;
        #pragma unroll
        for (int k = 0; k < 4; k++) {
            int i = tid + k * 256;          // 1024 float4 each
            w0s4[i] = gw0[i];
            w1s4[i] = gw1[i];
        }
        if (tid < CC) {
            u_s[tid] = g_upart[b * CC + tid] + g_upart[BB * CC + b * CC + tid];
            v_s[tid] = g_vpart[b * CC + tid] + g_vpart[BB * CC + b * CC + tid];
        }
    }
    __syncthreads();

    // p[o] = sum_c W0t[c][o] u[c] ; q[o] = sum_c W1t[c][o] v[c]
    if (tid < 128) {
        const int o = tid & 63;
        const bool isq = tid >= 64;
        const float* W = isq ? w1s : w0s;
        const float* uv = isq ? v_s : u_s;
        float s = 0.f;
        #pragma unroll 8
        for (int cc2 = 0; cc2 < CC; cc2++) s = fmaf(W[cc2 * CC + o], uv[cc2], s);
        (isq ? q_s : p_s)[o] = s;
    }
    __syncthreads();

    const int warp = tid >> 5, lane = tid & 31;
    const int ow = warp << 3;           // 8 o per warp
    const int ng = n0 + lane;           // 1 n per lane

    ull accA[4], accB[4];
    #pragma unroll
    for (int i = 0; i < 4; i++) { accA[i] = 0ull; accB[i] = 0ull; }

    const float* xp  = xs  + 2 * lane;
    const float* w0p = w0s + ow;
    const float* w1p = w1s + ow;

    #pragma unroll 8
    for (int k = 0; k < CC; k++) {
        ull xd = *(const ull*)(xp + k * 2 * TN);            // {x,x}
        ulonglong2 wa0 = *(const ulonglong2*)(w0p + k * CC);      // o0..o3
        ulonglong2 wb0 = *(const ulonglong2*)(w0p + k * CC + 4);  // o4..o7
        ulonglong2 wa1 = *(const ulonglong2*)(w1p + k * CC);
        ulonglong2 wb1 = *(const ulonglong2*)(w1p + k * CC + 4);
        accA[0] = fma2(wa0.x, xd, accA[0]);
        accA[1] = fma2(wa0.y, xd, accA[1]);
        accA[2] = fma2(wb0.x, xd, accA[2]);
        accA[3] = fma2(wb0.y, xd, accA[3]);
        accB[0] = fma2(wa1.x, xd, accB[0]);
        accB[1] = fma2(wa1.y, xd, accB[1]);
        accB[2] = fma2(wb1.x, xd, accB[2]);
        accB[3] = fma2(wb1.y, xd, accB[3]);
    }

    // epilogue
    const float an = g_a[b * NN + ng];
    const float dn = g_d[b * NN + ng];
    const ull ddp = pack2(dn * dn, dn * dn);
    const ull ap  = pack2(an, an);
    const ull dap = pack2(dn * an, dn * an);

    float* ob = out + (size_t)(b * CC) * NN + ng;
    #pragma unroll
    for (int j = 0; j < 4; j++) {
        const int o0 = ow + 2 * j;
        ull pp = *(const ull*)(p_s + o0);
        ull qq = *(const ull*)(q_s + o0);
        ull sc = *(const ull*)(g_scale + o0);
        ull sh = *(const ull*)(g_shift + o0);
        ull y = fma2(accB[j], ddp, accA[j]);
        y = fma2(pp, ap, y);
        y = fma2(qq, dap, y);
        y = fma2(y, sc, sh);
        float f0, f1;
        unpack2(y, f0, f1);
        ob[(size_t)o0 * NN]       = fmaxf(f0, 0.f);
        ob[(size_t)(o0 + 1) * NN] = fmaxf(f1, 0.f);
    }
}

// -----------------------------------------------------------------------------
extern "C" void kernel_launch(void* const* d_in, const int* in_sizes, int n_in,
                              void* d_out, int out_size) {
    const float* x      = (const float*)d_in[0];
    const float* w      = (const float*)d_in[1];
    const float* conv_w = (const float*)d_in[2];
    const float* conv_b = (const float*)d_in[3];
    const float* gamma  = (const float*)d_in[4];
    const float* beta   = (const float*)d_in[5];
    const float* mean   = (const float*)d_in[6];
    const float* var    = (const float*)d_in[7];
    float* out = (float*)d_out;

    const int smem = (CC * 2 * TN + 2 * CC * CC) * sizeof(float);  // 48 KB
    cudaFuncSetAttribute(k_fused, cudaFuncAttributeMaxDynamicSharedMemorySize, smem);

    k_fused<<<GRID, 256, smem>>>(x, w, conv_w, conv_b, gamma, beta, mean, var, out);
}

// round 6
// speedup vs baseline: 1.3997x; 1.3997x over previous
#include <cuda_runtime.h>

#define BB 4
#define CC 64
#define TN 64
#define NN 4096
#define GRID 256

typedef unsigned long long ull;

// scratch (allocation-free rule: __device__ globals, zero-initialized)
__device__ float g_a[BB * NN];
__device__ float g_d[BB * NN];
__device__ float g_u[BB * CC];
__device__ float g_v[BB * CC];
__device__ float g_W0t[CC * CC];     // [c][o]
__device__ float g_W1t[CC * CC];     // [c][o]
__device__ float g_scale[CC];
__device__ float g_shift[CC];
__device__ unsigned g_bar;           // monotonic barrier counter

// ---- f32x2 packed helpers ---------------------------------------------------
__device__ __forceinline__ ull pack2(float lo, float hi) {
    ull r; asm("mov.b64 %0, {%1, %2};" : "=l"(r) : "f"(lo), "f"(hi)); return r;
}
__device__ __forceinline__ void unpack2(ull v, float& lo, float& hi) {
    asm("mov.b64 {%0, %1}, %2;" : "=f"(lo), "=f"(hi) : "l"(v));
}
__device__ __forceinline__ ull fma2(ull a, ull b, ull c) {
    ull d; asm("fma.rn.f32x2 %0, %1, %2, %3;" : "=l"(d) : "l"(a), "l"(b), "l"(c)); return d;
}
__device__ __forceinline__ ull mul2(ull a, ull b) {
    ull d; asm("mul.rn.f32x2 %0, %1, %2;" : "=l"(d) : "l"(a), "l"(b)); return d;
}

__device__ __forceinline__ float relutanh(float x) {
    if (x <= 0.f) return 0.f;
    float e = __expf(-2.f * x);
    return (1.f - e) * __frcp_rn(1.f + e);
}

// -----------------------------------------------------------------------------
// Single fused kernel. grid=256, 256 threads, 48KB dynamic smem, <=128 regs.
// Phase 1: block (b = blk>>6, c = blk&63): a,d in regs + u,v reduction;
//          c==0 writes g_a/g_d; b==0 transposes conv_w row c; (0,0) folds BN.
// Barrier: device-wide monotonic counter.
// Phase 2: block (b, tile = blk&63), n0 = tile*64. warp = 8 o, lane = 2 n.
//          Merged-acc f32x2 GEMM (W0*x + W1*(d^2 x)) + rank-1 + BN + ReLU.
// -----------------------------------------------------------------------------
__global__ void __launch_bounds__(256, 2) k_fused(
        const float* __restrict__ x,
        const float* __restrict__ w,
        const float* __restrict__ conv_w,
        const float* __restrict__ conv_b,
        const float* __restrict__ gamma,
        const float* __restrict__ beta,
        const float* __restrict__ mean,
        const float* __restrict__ var,
        float* __restrict__ out) {
    extern __shared__ float sm[];
    float* xs  = sm;                  // [64][64] plain x      16KB
    float* w0s = sm + CC * TN;        // [c][o]                16KB
    float* w1s = w0s + CC * CC;       //                       16KB
    __shared__ float p_s[CC], q_s[CC], u_s[CC], v_s[CC];
    __shared__ float red[8], red2[8];
    __shared__ float S_sh;

    const int tid = threadIdx.x;
    const int blk = blockIdx.x;
    const int b = blk >> 6;
    const int c = blk & 63;

    // ================= Phase 1 =================
    {
        const float4* w4 = (const float4*)(w + b * NN);
        float avr[16], dvr[16];
        float s = 0.f;
        #pragma unroll
        for (int k = 0; k < 4; k++) {
            float4 wv = w4[tid + k * 256];
            avr[k*4+0] = relutanh(wv.x);
            avr[k*4+1] = relutanh(wv.y);
            avr[k*4+2] = relutanh(wv.z);
            avr[k*4+3] = relutanh(wv.w);
            s += avr[k*4+0] + avr[k*4+1] + avr[k*4+2] + avr[k*4+3];
        }
        #pragma unroll
        for (int off = 16; off; off >>= 1) s += __shfl_down_sync(0xffffffffu, s, off);
        if ((tid & 31) == 0) red[tid >> 5] = s;
        __syncthreads();
        if (tid == 0) {
            float t = 0.f;
            #pragma unroll
            for (int i = 0; i < 8; i++) t += red[i];
            S_sh = t;
        }
        __syncthreads();
        const float S = S_sh;
        #pragma unroll
        for (int i = 0; i < 16; i++) dvr[i] = rsqrtf(fmaf(avr[i], S, 1.f));

        if (c == 0) {
            #pragma unroll
            for (int k = 0; k < 4; k++) {
                ((float4*)(g_a + b * NN))[tid + k * 256] =
                    make_float4(avr[k*4+0], avr[k*4+1], avr[k*4+2], avr[k*4+3]);
                ((float4*)(g_d + b * NN))[tid + k * 256] =
                    make_float4(dvr[k*4+0], dvr[k*4+1], dvr[k*4+2], dvr[k*4+3]);
            }
        }
        if (b == 0) {
            if (tid < CC) {
                g_W0t[c * CC + tid] = conv_w[tid * 128 + c];
                g_W1t[c * CC + tid] = conv_w[tid * 128 + CC + c];
            }
            if (c == 0 && tid >= 64 && tid < 128) {
                int o = tid - 64;
                float sc = gamma[o] * rsqrtf(var[o] + 1e-5f);
                g_scale[o] = sc;
                g_shift[o] = fmaf(conv_b[o] - mean[o], sc, beta[o]);
            }
        }

        // u = sum x*a ; v = sum x*a*d for channel (b,c)
        const float4* x4 = (const float4*)(x + (size_t)(b * CC + c) * NN);
        float su = 0.f, sv = 0.f;
        #pragma unroll
        for (int k = 0; k < 4; k++) {
            float4 xv = x4[tid + k * 256];
            float t0 = xv.x * avr[k*4+0], t1 = xv.y * avr[k*4+1];
            float t2 = xv.z * avr[k*4+2], t3 = xv.w * avr[k*4+3];
            su += t0 + t1 + t2 + t3;
            sv += t0 * dvr[k*4+0] + t1 * dvr[k*4+1] + t2 * dvr[k*4+2] + t3 * dvr[k*4+3];
        }
        #pragma unroll
        for (int off = 16; off; off >>= 1) {
            su += __shfl_down_sync(0xffffffffu, su, off);
            sv += __shfl_down_sync(0xffffffffu, sv, off);
        }
        if ((tid & 31) == 0) { red[tid >> 5] = su; red2[tid >> 5] = sv; }
        __syncthreads();
        if (tid == 0) {
            float tu = 0.f, tv = 0.f;
            #pragma unroll
            for (int i = 0; i < 8; i++) { tu += red[i]; tv += red2[i]; }
            g_u[b * CC + c] = tu;
            g_v[b * CC + c] = tv;
        }
    }

    // ================= device-wide barrier =================
    __threadfence();
    __syncthreads();
    if (tid == 0) {
        unsigned old = atomicAdd(&g_bar, 1u);
        unsigned target = (old & ~(unsigned)(GRID - 1)) + GRID;
        unsigned vcur;
        do { vcur = *(volatile unsigned*)&g_bar; } while ((int)(vcur - target) < 0);
    }
    __syncthreads();

    // ================= Phase 2 =================
    const int n0 = c * TN;

    // stage: plain x tile [64][64], weights, u/v
    {
        const float* xb = x + (size_t)(b * CC) * NN + n0;
        float4* xs4 = (float4*)xs;
        #pragma unroll
        for (int k = 0; k < 4; k++) {
            int i = tid + k * 256;          // 1024 float4 = 64 rows x 16
            int cc2 = i >> 4, j = i & 15;
            xs4[i] = ((const float4*)(xb + cc2 * NN))[j];
        }
        float4* w0s4 = (float4*)w0s;
        float4* w1s4 = (float4*)w1s;
        const float4* gw0 = (const float4*)g_W0t;
        const float4* gw1 = (const float4*)g_W1t;
        #pragma unroll
        for (int k = 0; k < 4; k++) {
            int i = tid + k * 256;          // 1024 float4 each
            w0s4[i] = gw0[i];
            w1s4[i] = gw1[i];
        }
        if (tid < CC) {
            u_s[tid] = g_u[b * CC + tid];
            v_s[tid] = g_v[b * CC + tid];
        }
    }
    __syncthreads();

    // p[o] = sum_c W0t[c][o] u[c] ; q[o] = sum_c W1t[c][o] v[c]
    if (tid < 128) {
        const int o = tid & 63;
        const bool isq = tid >= 64;
        const float* W = isq ? w1s : w0s;
        const float* uv = isq ? v_s : u_s;
        float s = 0.f;
        #pragma unroll 8
        for (int cc2 = 0; cc2 < CC; cc2++) s = fmaf(W[cc2 * CC + o], uv[cc2], s);
        (isq ? q_s : p_s)[o] = s;
    }
    __syncthreads();

    const int warp = tid >> 5, lane = tid & 31;
    const int ow = warp << 3;           // 8 o per warp (4 o-pairs)
    const int ng = n0 + 2 * lane;       // 2 n per lane

    // per-thread loop-invariant {d^2, d^2} for each of the 2 n
    const float2 a2 = *(const float2*)(g_a + b * NN + ng);
    const float2 d2 = *(const float2*)(g_d + b * NN + ng);
    const ull ddp0 = pack2(d2.x * d2.x, d2.x * d2.x);
    const ull ddp1 = pack2(d2.y * d2.y, d2.y * d2.y);

    ull acc[4][2];                      // [o-pair][n]
    #pragma unroll
    for (int i = 0; i < 4; i++) { acc[i][0] = 0ull; acc[i][1] = 0ull; }

    const float* xp  = xs  + 2 * lane;
    const float* w0p = w0s + ow;
    const float* w1p = w1s + ow;

    #pragma unroll 8
    for (int k = 0; k < CC; k++) {
        float2 xv = *(const float2*)(xp + k * TN);              // LDS.64, 2 wf
        ull xd0 = pack2(xv.x, xv.x);
        ull xd1 = pack2(xv.y, xv.y);
        ull xq0 = mul2(xd0, ddp0);                              // {d0^2 x0, ...}
        ull xq1 = mul2(xd1, ddp1);
        ulonglong2 wa0 = *(const ulonglong2*)(w0p + k * CC);        // o0..o3
        ulonglong2 wb0 = *(const ulonglong2*)(w0p + k * CC + 4);    // o4..o7
        ulonglong2 wa1 = *(const ulonglong2*)(w1p + k * CC);
        ulonglong2 wb1 = *(const ulonglong2*)(w1p + k * CC + 4);
        acc[0][0] = fma2(wa0.x, xd0, acc[0][0]);
        acc[0][1] = fma2(wa0.x, xd1, acc[0][1]);
        acc[1][0] = fma2(wa0.y, xd0, acc[1][0]);
        acc[1][1] = fma2(wa0.y, xd1, acc[1][1]);
        acc[2][0] = fma2(wb0.x, xd0, acc[2][0]);
        acc[2][1] = fma2(wb0.x, xd1, acc[2][1]);
        acc[3][0] = fma2(wb0.y, xd0, acc[3][0]);
        acc[3][1] = fma2(wb0.y, xd1, acc[3][1]);
        acc[0][0] = fma2(wa1.x, xq0, acc[0][0]);
        acc[0][1] = fma2(wa1.x, xq1, acc[0][1]);
        acc[1][0] = fma2(wa1.y, xq0, acc[1][0]);
        acc[1][1] = fma2(wa1.y, xq1, acc[1][1]);
        acc[2][0] = fma2(wb1.x, xq0, acc[2][0]);
        acc[2][1] = fma2(wb1.x, xq1, acc[2][1]);
        acc[3][0] = fma2(wb1.y, xq0, acc[3][0]);
        acc[3][1] = fma2(wb1.y, xq1, acc[3][1]);
    }

    // epilogue: y = acc + p*a_n + q*(d*a)_n ; BN ; ReLU
    const ull ap0  = pack2(a2.x, a2.x);
    const ull ap1  = pack2(a2.y, a2.y);
    const ull dap0 = pack2(d2.x * a2.x, d2.x * a2.x);
    const ull dap1 = pack2(d2.y * a2.y, d2.y * a2.y);

    float* ob = out + (size_t)(b * CC) * NN + ng;
    #pragma unroll
    for (int j = 0; j < 4; j++) {
        const int o0 = ow + 2 * j;
        ull pp = *(const ull*)(p_s + o0);
        ull qq = *(const ull*)(q_s + o0);
        ull sc = *(const ull*)(g_scale + o0);
        ull sh = *(const ull*)(g_shift + o0);
        ull y0 = fma2(pp, ap0, acc[j][0]);
        y0 = fma2(qq, dap0, y0);
        y0 = fma2(y0, sc, sh);
        ull y1 = fma2(pp, ap1, acc[j][1]);
        y1 = fma2(qq, dap1, y1);
        y1 = fma2(y1, sc, sh);
        float f00, f10, f01, f11;
        unpack2(y0, f00, f10);     // (o0,n0), (o1,n0)
        unpack2(y1, f01, f11);     // (o0,n1), (o1,n1)
        f00 = fmaxf(f00, 0.f); f01 = fmaxf(f01, 0.f);
        f10 = fmaxf(f10, 0.f); f11 = fmaxf(f11, 0.f);
        *(float2*)(ob + (size_t)o0 * NN)       = make_float2(f00, f01);
        *(float2*)(ob + (size_t)(o0 + 1) * NN) = make_float2(f10, f11);
    }
}

// -----------------------------------------------------------------------------
extern "C" void kernel_launch(void* const* d_in, const int* in_sizes, int n_in,
                              void* d_out, int out_size) {
    const float* x      = (const float*)d_in[0];
    const float* w      = (const float*)d_in[1];
    const float* conv_w = (const float*)d_in[2];
    const float* conv_b = (const float*)d_in[3];
    const float* gamma  = (const float*)d_in[4];
    const float* beta   = (const float*)d_in[5];
    const float* mean   = (const float*)d_in[6];
    const float* var    = (const float*)d_in[7];
    float* out = (float*)d_out;

    const int smem = (CC * TN + 2 * CC * CC) * sizeof(float);  // 48 KB
    cudaFuncSetAttribute(k_fused, cudaFuncAttributeMaxDynamicSharedMemorySize, smem);

    k_fused<<<GRID, 256, smem>>>(x, w, conv_w, conv_b, gamma, beta, mean, var, out);
}